// round 16
// baseline (speedup 1.0000x reference)
#include <cuda_runtime.h>
#include <math.h>

// ToneStack: 3 cascaded low-shelf biquads over x:[64, 480000] fp32.
// Blocked-recurrence decomposition, 3 kernels:
//   pass_zero : block 0 runs fp32 setup (coefs + T/Tg/Tsg) then publishes a
//               flag; all blocks serially filter their chunks from zero state
//               (first-tile LDGs issued before the spin to hide it) -> finals
//   scan_fused: per-row 3-level affine scan (smem-staged); resets the flag
//   pass_final: per-chunk serial filter from exact entry state (proven 37us)
// NOTE: all smem arrays accessed as float4 carry __align__(16) — shared
// floats otherwise get 4B alignment and sbuf shifted behind setup's arrays
// caused R15's misaligned-address fault.

#define TLEN   480000
#define NROW   64
#define CHUNK  128
#define CROW   3750            // chunks per row
#define NCH    (NROW * CROW)   // 240000
#define NWARP  (NCH / 32)      // 7500
#define PBLK   (NWARP / 4)     // 1875 blocks of 4 warps
#define NGSZ   30              // chunks per group
#define NGROUP 125             // groups per row
#define NSUPG  5
#define NSUP   25
#define GPAD   182             // group row stride (even -> float2 copies)
#define SCAN_SMEM (NGROUP * GPAD * 4)

__device__ float g_coef[15];          // per stage: b0, c1, c2, -a1, -a2
__device__ float g_T[36];             // A^CHUNK
__device__ float g_Tg[36];            // T^NGSZ
__device__ float g_Tsg[36];           // Tg^NSUPG
__device__ float g_states[NCH * 6];   // finals, then overwritten with entries
__device__ int   g_ready;             // setup-done flag (reset by scan_fused)

// ---------------------------------------------------------------- setup ----

__device__ void shelf_coefs_f(float fc, float gdb, float Q, float* out) {
    const float PI = 3.14159265358979323846f;
    float A  = exp10f(gdb * (1.0f / 40.0f));
    float w0 = 2.0f * PI * fc / 48000.0f;
    float al = sinf(w0) / (2.0f * Q);
    float cw = cosf(w0);
    float sq = sqrtf(A);
    float b0 = A * ((A + 1.0f) - (A - 1.0f) * cw + 2.0f * sq * al);
    float b1 = 2.0f * A * ((A - 1.0f) - (A + 1.0f) * cw);
    float b2 = A * ((A + 1.0f) - (A - 1.0f) * cw - 2.0f * sq * al);
    float a0 = (A + 1.0f) + (A - 1.0f) * cw + 2.0f * sq * al;
    float a1 = -2.0f * ((A - 1.0f) + (A + 1.0f) * cw);
    float a2 = (A + 1.0f) + (A - 1.0f) * cw - 2.0f * sq * al;
    float inv = 1.0f / a0;
    b0 *= inv; b1 *= inv; b2 *= inv; a1 *= inv; a2 *= inv;
    out[0] = b0;
    out[1] = b1 - a1 * b0;   // c1
    out[2] = b2 - a2 * b0;   // c2
    out[3] = -a1;
    out[4] = -a2;
}

#define MATMUL(D, A_, B_)                                                     \
    do {                                                                      \
        if (tid < 36) {                                                       \
            int r_ = tid / 6, c_ = tid % 6;                                   \
            float acc_ = 0.f;                                                 \
            for (int k_ = 0; k_ < 6; k_++)                                    \
                acc_ += (A_)[r_ * 6 + k_] * (B_)[k_ * 6 + c_];                \
            (D)[tid] = acc_;                                                  \
        }                                                                     \
        __syncthreads();                                                      \
    } while (0)

// Runs inside pass_zero block 0 (all 128 threads participate in barriers).
__device__ void do_setup(const float* lg, const float* mg, const float* mfc,
                         const float* mq, const float* hg) {
    __shared__ __align__(16) float scoef[16];
    __shared__ __align__(16) float M0[36], M1[36], M2[36], M3[36], M4[36];
    int tid = threadIdx.x;

    if (tid == 0) {
        float c[5];
        shelf_coefs_f(120.0f, *lg, 0.707f, c);
        for (int i = 0; i < 5; i++) { scoef[i] = c[i]; g_coef[i] = c[i]; }
    } else if (tid == 1) {
        float c[5];
        shelf_coefs_f(*mfc, *mg, *mq, c);
        for (int i = 0; i < 5; i++) { scoef[5 + i] = c[i]; g_coef[5 + i] = c[i]; }
    } else if (tid == 2) {
        float c[5];
        shelf_coefs_f(4000.0f, *hg, 0.707f, c);
        for (int i = 0; i < 5; i++) { scoef[10 + i] = c[i]; g_coef[10 + i] = c[i]; }
    }
    __syncthreads();

    // One-step 6x6 homogeneous matrix A: column j = step(e_j, x=0)
    if (tid < 6) {
        float z[6] = {0, 0, 0, 0, 0, 0};
        z[tid] = 1.0f;
        float u = 0.0f;
        float ns[6];
        for (int st = 0; st < 3; st++) {
            float b0  = scoef[st * 5 + 0], c1 = scoef[st * 5 + 1], c2 = scoef[st * 5 + 2];
            float na1 = scoef[st * 5 + 3], na2 = scoef[st * 5 + 4];
            float z1 = z[2 * st], z2 = z[2 * st + 1];
            float y = b0 * u + z1;
            ns[2 * st]     = c1 * u + na1 * z1 + z2;
            ns[2 * st + 1] = c2 * u + na2 * z1;
            u = y;
        }
        for (int i = 0; i < 6; i++) M0[i * 6 + tid] = ns[i];
    }
    __syncthreads();

    // T = A^128 : 7 squarings (ends in M1)
    MATMUL(M1, M0, M0);   // A^2
    MATMUL(M0, M1, M1);   // A^4
    MATMUL(M1, M0, M0);   // A^8
    MATMUL(M0, M1, M1);   // A^16
    MATMUL(M1, M0, M0);   // A^32
    MATMUL(M0, M1, M1);   // A^64
    MATMUL(M1, M0, M0);   // A^128 = T
    if (tid < 36) { g_T[tid] = M1[tid]; M0[tid] = M1[tid]; }
    __syncthreads();

    // Tg = T^30 ; Tsg = Tg^5
    MATMUL(M1, M0, M0);   // T^2
    MATMUL(M2, M1, M1);   // T^4
    MATMUL(M3, M2, M2);   // T^8
    MATMUL(M4, M3, M3);   // T^16
    MATMUL(M0, M4, M3);   // T^24
    MATMUL(M3, M0, M2);   // T^28
    MATMUL(M2, M3, M1);   // T^30 = Tg
    if (tid < 36) g_Tg[tid] = M2[tid];
    __syncthreads();
    MATMUL(M1, M2, M2);   // Tg^2
    MATMUL(M0, M1, M1);   // Tg^4
    MATMUL(M4, M0, M2);   // Tg^5 = Tsg
    if (tid < 36) g_Tsg[tid] = M4[tid];
    __syncthreads();

    // publish
    __threadfence();
    if (tid == 0) atomicExch(&g_ready, 1);
}

// -------------------------------------------------------------- filtering --

__device__ __forceinline__ float step_all(float u, float z[6], const float k[15]) {
    float y0 = fmaf(k[0], u, z[0]);
    float t0 = fmaf(k[3], z[0], z[1]);
    z[1] = fmaf(k[2], u, k[4] * z[0]);
    z[0] = fmaf(k[1], u, t0);
    float y1 = fmaf(k[5], y0, z[2]);
    float t1 = fmaf(k[8], z[2], z[3]);
    z[3] = fmaf(k[7], y0, k[9] * z[2]);
    z[2] = fmaf(k[6], y0, t1);
    float y2 = fmaf(k[10], y1, z[4]);
    float t2 = fmaf(k[13], z[4], z[5]);
    z[5] = fmaf(k[12], y1, k[14] * z[4]);
    z[4] = fmaf(k[11], y1, t2);
    return y2;
}

// Tile: 32 chunks x 32 samples, rows padded to 36 floats. seg = lane>>3,
// off = (lane&7)*4: every LDG/STG.128 covers 4 full 128B lines.

// pass_zero: serial filter from zero state; only the final state is kept.
// Block 0 performs setup first; others spin (overlapped with first-tile LDGs).
__global__ __launch_bounds__(128) void pass_zero(const float* __restrict__ x,
                                                 const float* lg, const float* mg,
                                                 const float* mfc, const float* mq,
                                                 const float* hg) {
    __shared__ __align__(16) float sbuf[4][32][36];
    int wslot = threadIdx.x >> 5;
    int w = blockIdx.x * 4 + wslot;
    int lane = threadIdx.x & 31;
    float (*buf)[36] = sbuf[wslot];
    const float* xw = x + (size_t)w * (32 * CHUNK);

    int seg = lane >> 3;
    int off = (lane & 7) * 4;

    if (blockIdx.x == 0) {
        do_setup(lg, mg, mfc, mq, hg);
    }

    // issue first-tile loads before the spin so LDG latency overlaps it
    float4 pre[8];
#pragma unroll
    for (int q = 0; q < 8; q++)
        pre[q] = *(const float4*)(xw + (q * 4 + seg) * CHUNK + off);

    if (blockIdx.x != 0) {
        volatile int* vf = &g_ready;
        while (*vf == 0) __nanosleep(64);
        __threadfence();
    }

    float k[15];
#pragma unroll
    for (int i = 0; i < 15; i++) k[i] = g_coef[i];
    float z[6] = {0, 0, 0, 0, 0, 0};

#pragma unroll
    for (int t = 0; t < CHUNK / 32; t++) {
#pragma unroll
        for (int q = 0; q < 8; q++)
            *(float4*)&buf[q * 4 + seg][off] = pre[q];
        __syncwarp();
        if (t < CHUNK / 32 - 1) {
#pragma unroll
            for (int q = 0; q < 8; q++)
                pre[q] = *(const float4*)(xw + (q * 4 + seg) * CHUNK + (t + 1) * 32 + off);
        }
        const float4* my = (const float4*)buf[lane];
#pragma unroll
        for (int j = 0; j < 8; j++) {
            float4 v = my[j];
            step_all(v.x, z, k);
            step_all(v.y, z, k);
            step_all(v.z, z, k);
            step_all(v.w, z, k);
        }
        __syncwarp();
    }
    float* f = &g_states[(size_t)(w * 32 + lane) * 6];
#pragma unroll
    for (int j = 0; j < 6; j++) f[j] = z[j];
}

__global__ __launch_bounds__(128) void pass_final(const float* __restrict__ x,
                                                  float* __restrict__ y) {
    __shared__ __align__(16) float sbuf[4][32][36];
    int wslot = threadIdx.x >> 5;
    int w = blockIdx.x * 4 + wslot;
    int lane = threadIdx.x & 31;
    float (*buf)[36] = sbuf[wslot];
    const float* xw = x + (size_t)w * (32 * CHUNK);
    float* yw = y + (size_t)w * (32 * CHUNK);

    float k[15];
#pragma unroll
    for (int i = 0; i < 15; i++) k[i] = g_coef[i];
    float z[6];
    const float* si = &g_states[(size_t)(w * 32 + lane) * 6];
#pragma unroll
    for (int j = 0; j < 6; j++) z[j] = si[j];

    int seg = lane >> 3;
    int off = (lane & 7) * 4;

    float4 pre[8];
#pragma unroll
    for (int q = 0; q < 8; q++)
        pre[q] = *(const float4*)(xw + (q * 4 + seg) * CHUNK + off);

#pragma unroll
    for (int t = 0; t < CHUNK / 32; t++) {
#pragma unroll
        for (int q = 0; q < 8; q++)
            *(float4*)&buf[q * 4 + seg][off] = pre[q];
        __syncwarp();
        if (t < CHUNK / 32 - 1) {
#pragma unroll
            for (int q = 0; q < 8; q++)
                pre[q] = *(const float4*)(xw + (q * 4 + seg) * CHUNK + (t + 1) * 32 + off);
        }
        float4* my = (float4*)buf[lane];
#pragma unroll
        for (int j = 0; j < 8; j++) {
            float4 v = my[j];
            float4 o;
            o.x = step_all(v.x, z, k);
            o.y = step_all(v.y, z, k);
            o.z = step_all(v.z, z, k);
            o.w = step_all(v.w, z, k);
            my[j] = o;
        }
        __syncwarp();
#pragma unroll
        for (int q = 0; q < 8; q++) {
            float4 v = *(const float4*)&buf[q * 4 + seg][off];
            *(float4*)(yw + (q * 4 + seg) * CHUNK + t * 32 + off) = v;
        }
        __syncwarp();
    }
}

// ------------------------------------------------------------ fused scan --

__device__ __forceinline__ void affine_step(float s[6], const float fv[6],
                                            const float T[36]) {
    float ns[6];
#pragma unroll
    for (int j = 0; j < 6; j++) {
        float acc = fv[j];
#pragma unroll
        for (int kk = 0; kk < 6; kk++) acc = fmaf(T[j * 6 + kk], s[kk], acc);
        ns[j] = acc;
    }
#pragma unroll
    for (int j = 0; j < 6; j++) s[j] = ns[j];
}

// One block per row; row's 22500 floats staged in padded dynamic smem via
// float2 bulk copies (256 threads); 3-level scan; entries written back.
// Block 0 also resets g_ready for the next graph replay.
__global__ __launch_bounds__(256) void scan_fused() {
    extern __shared__ __align__(16) float sf[];   // NGROUP * GPAD floats
    __shared__ __align__(16) float sT[36], sTg[36], sTsg[36];
    __shared__ __align__(16) float grp[NGROUP][6];
    __shared__ __align__(16) float sup[NSUP][6];
    int r = blockIdx.x, tid = threadIdx.x;
    float* gs = &g_states[(size_t)r * CROW * 6];

    if (r == 0 && tid == 0) atomicExch(&g_ready, 0);   // reset for next replay

    for (int i2 = tid; i2 < CROW * 6 / 2; i2 += 256) {
        int e = 2 * i2;
        int g = e / (NGSZ * 6);
        int woff = e - g * (NGSZ * 6);
        ((float2*)sf)[g * (GPAD / 2) + woff / 2] = ((const float2*)gs)[i2];
    }
    if (tid < 36) { sT[tid] = g_T[tid]; sTg[tid] = g_Tg[tid]; sTsg[tid] = g_Tsg[tid]; }
    __syncthreads();

    // phase 1: zero-entry scan within each group -> group final
    if (tid < NGROUP) {
        float T[36];
#pragma unroll
        for (int i = 0; i < 36; i++) T[i] = sT[i];
        const float* f = &sf[tid * GPAD];
        float s[6] = {0, 0, 0, 0, 0, 0};
        for (int i = 0; i < NGSZ; i++) {
            float fv[6];
#pragma unroll
            for (int j = 0; j < 6; j++) fv[j] = f[i * 6 + j];
            affine_step(s, fv, T);
        }
#pragma unroll
        for (int j = 0; j < 6; j++) grp[tid][j] = s[j];
    }
    __syncthreads();

    // phase 2a: zero-entry scan of 5 group finals -> supergroup final
    if (tid < NSUP) {
        float T[36];
#pragma unroll
        for (int i = 0; i < 36; i++) T[i] = sTg[i];
        float s[6] = {0, 0, 0, 0, 0, 0};
        for (int i = 0; i < NSUPG; i++) affine_step(s, grp[tid * NSUPG + i], T);
#pragma unroll
        for (int j = 0; j < 6; j++) sup[tid][j] = s[j];
    }
    __syncthreads();

    // phase 2b: serial scan over supergroups; sup[] becomes entry states
    if (tid == 0) {
        float T[36];
#pragma unroll
        for (int i = 0; i < 36; i++) T[i] = sTsg[i];
        float s[6] = {0, 0, 0, 0, 0, 0};
        for (int g = 0; g < NSUP; g++) {
            float fv[6];
#pragma unroll
            for (int j = 0; j < 6; j++) { fv[j] = sup[g][j]; sup[g][j] = s[j]; }
            affine_step(s, fv, T);
        }
    }
    __syncthreads();

    // phase 2c: group entry states from supergroup entry
    if (tid < NSUP) {
        float T[36];
#pragma unroll
        for (int i = 0; i < 36; i++) T[i] = sTg[i];
        float s[6];
#pragma unroll
        for (int j = 0; j < 6; j++) s[j] = sup[tid][j];
        for (int i = 0; i < NSUPG; i++) {
            float fv[6];
            int gi = tid * NSUPG + i;
#pragma unroll
            for (int j = 0; j < 6; j++) { fv[j] = grp[gi][j]; grp[gi][j] = s[j]; }
            affine_step(s, fv, T);
        }
    }
    __syncthreads();

    // phase 3: per-chunk entry states, overwrite staged finals
    if (tid < NGROUP) {
        float T[36];
#pragma unroll
        for (int i = 0; i < 36; i++) T[i] = sT[i];
        float* f = &sf[tid * GPAD];
        float s[6];
#pragma unroll
        for (int j = 0; j < 6; j++) s[j] = grp[tid][j];
        for (int i = 0; i < NGSZ; i++) {
            float fv[6];
#pragma unroll
            for (int j = 0; j < 6; j++) { fv[j] = f[i * 6 + j]; f[i * 6 + j] = s[j]; }
            affine_step(s, fv, T);
        }
    }
    __syncthreads();

    for (int i2 = tid; i2 < CROW * 6 / 2; i2 += 256) {
        int e = 2 * i2;
        int g = e / (NGSZ * 6);
        int woff = e - g * (NGSZ * 6);
        ((float2*)gs)[i2] = ((const float2*)sf)[g * (GPAD / 2) + woff / 2];
    }
}

// ----------------------------------------------------------------- launch --

extern "C" void kernel_launch(void* const* d_in, const int* in_sizes, int n_in,
                              void* d_out, int out_size) {
    const float* x   = (const float*)d_in[0];
    const float* lg  = (const float*)d_in[1];
    const float* mg  = (const float*)d_in[2];
    const float* mfc = (const float*)d_in[3];
    const float* mq  = (const float*)d_in[4];
    const float* hg  = (const float*)d_in[5];
    float* y = (float*)d_out;

    cudaFuncSetAttribute(scan_fused, cudaFuncAttributeMaxDynamicSharedMemorySize,
                         SCAN_SMEM);

    pass_zero<<<PBLK, 128>>>(x, lg, mg, mfc, mq, hg);
    scan_fused<<<NROW, 256, SCAN_SMEM>>>();
    pass_final<<<PBLK, 128>>>(x, y);
}

// round 17
// speedup vs baseline: 1.0732x; 1.0732x over previous
#include <cuda_runtime.h>
#include <math.h>

// ToneStack: 3 cascaded low-shelf biquads over x:[64, 480000] fp32.
// Blocked-recurrence decomposition, 3 kernels (NO setup kernel — every block
// redundantly derives the fp32 coefficients in ~300 cycles; scan blocks also
// build the T/Tg/Tsg matrix tables in-block):
//   pass_zero : per-chunk serial filter from zero state -> finals
//   scan_fused: per-row 3-level affine scan (smem-staged)
//   pass_final: per-chunk serial filter from exact entry state (proven 37us)

#define TLEN   480000
#define NROW   64
#define CHUNK  128
#define CROW   3750            // chunks per row
#define NCH    (NROW * CROW)   // 240000
#define NWARP  (NCH / 32)      // 7500
#define PBLK   (NWARP / 4)     // 1875 blocks of 4 warps
#define NGSZ   30              // chunks per group
#define NGROUP 125             // groups per row
#define NSUPG  5
#define NSUP   25
#define GPAD   182             // group row stride (even -> float2 copies)
#define SCAN_SMEM (NGROUP * GPAD * 4)

__device__ float g_states[NCH * 6];   // finals, then overwritten with entries

// ----------------------------------------------------------- coefficients --

__device__ __forceinline__ void shelf_coefs_f(float fc, float gdb, float Q,
                                              float* out) {
    const float PI = 3.14159265358979323846f;
    float A  = exp10f(gdb * (1.0f / 40.0f));
    float w0 = 2.0f * PI * fc / 48000.0f;
    float al = sinf(w0) / (2.0f * Q);
    float cw = cosf(w0);
    float sq = sqrtf(A);
    float b0 = A * ((A + 1.0f) - (A - 1.0f) * cw + 2.0f * sq * al);
    float b1 = 2.0f * A * ((A - 1.0f) - (A + 1.0f) * cw);
    float b2 = A * ((A + 1.0f) - (A - 1.0f) * cw - 2.0f * sq * al);
    float a0 = (A + 1.0f) + (A - 1.0f) * cw + 2.0f * sq * al;
    float a1 = -2.0f * ((A - 1.0f) + (A + 1.0f) * cw);
    float a2 = (A + 1.0f) + (A - 1.0f) * cw - 2.0f * sq * al;
    float inv = 1.0f / a0;
    b0 *= inv; b1 *= inv; b2 *= inv; a1 *= inv; a2 *= inv;
    out[0] = b0;
    out[1] = b1 - a1 * b0;   // c1
    out[2] = b2 - a2 * b0;   // c2
    out[3] = -a1;
    out[4] = -a2;
}

// threads 0..2 fill scoef[0..14]; caller must __syncthreads() afterwards.
__device__ __forceinline__ void block_coefs(float* scoef,
                                            const float* lg, const float* mg,
                                            const float* mfc, const float* mq,
                                            const float* hg) {
    int tid = threadIdx.x;
    if (tid == 0) {
        float c[5];
        shelf_coefs_f(120.0f, *lg, 0.707f, c);
        for (int i = 0; i < 5; i++) scoef[i] = c[i];
    } else if (tid == 1) {
        float c[5];
        shelf_coefs_f(*mfc, *mg, *mq, c);
        for (int i = 0; i < 5; i++) scoef[5 + i] = c[i];
    } else if (tid == 2) {
        float c[5];
        shelf_coefs_f(4000.0f, *hg, 0.707f, c);
        for (int i = 0; i < 5; i++) scoef[10 + i] = c[i];
    }
}

// -------------------------------------------------------------- filtering --

__device__ __forceinline__ float step_all(float u, float z[6], const float k[15]) {
    float y0 = fmaf(k[0], u, z[0]);
    float t0 = fmaf(k[3], z[0], z[1]);
    z[1] = fmaf(k[2], u, k[4] * z[0]);
    z[0] = fmaf(k[1], u, t0);
    float y1 = fmaf(k[5], y0, z[2]);
    float t1 = fmaf(k[8], z[2], z[3]);
    z[3] = fmaf(k[7], y0, k[9] * z[2]);
    z[2] = fmaf(k[6], y0, t1);
    float y2 = fmaf(k[10], y1, z[4]);
    float t2 = fmaf(k[13], z[4], z[5]);
    z[5] = fmaf(k[12], y1, k[14] * z[4]);
    z[4] = fmaf(k[11], y1, t2);
    return y2;
}

// Tile: 32 chunks x 32 samples, rows padded to 36 floats. seg = lane>>3,
// off = (lane&7)*4: every LDG/STG.128 covers 4 full 128B lines.

// pass_zero: serial filter from zero state; only the final state is kept.
__global__ __launch_bounds__(128) void pass_zero(const float* __restrict__ x,
                                                 const float* lg, const float* mg,
                                                 const float* mfc, const float* mq,
                                                 const float* hg) {
    __shared__ __align__(16) float sbuf[4][32][36];
    __shared__ __align__(16) float scoef[16];
    int wslot = threadIdx.x >> 5;
    int w = blockIdx.x * 4 + wslot;
    int lane = threadIdx.x & 31;
    float (*buf)[36] = sbuf[wslot];
    const float* xw = x + (size_t)w * (32 * CHUNK);

    int seg = lane >> 3;
    int off = (lane & 7) * 4;

    block_coefs(scoef, lg, mg, mfc, mq, hg);

    // first-tile loads issued before the barrier (hides coef latency)
    float4 pre[8];
#pragma unroll
    for (int q = 0; q < 8; q++)
        pre[q] = *(const float4*)(xw + (q * 4 + seg) * CHUNK + off);
    __syncthreads();

    float k[15];
#pragma unroll
    for (int i = 0; i < 15; i++) k[i] = scoef[i];
    float z[6] = {0, 0, 0, 0, 0, 0};

#pragma unroll
    for (int t = 0; t < CHUNK / 32; t++) {
#pragma unroll
        for (int q = 0; q < 8; q++)
            *(float4*)&buf[q * 4 + seg][off] = pre[q];
        __syncwarp();
        if (t < CHUNK / 32 - 1) {
#pragma unroll
            for (int q = 0; q < 8; q++)
                pre[q] = *(const float4*)(xw + (q * 4 + seg) * CHUNK + (t + 1) * 32 + off);
        }
        const float4* my = (const float4*)buf[lane];
#pragma unroll
        for (int j = 0; j < 8; j++) {
            float4 v = my[j];
            step_all(v.x, z, k);
            step_all(v.y, z, k);
            step_all(v.z, z, k);
            step_all(v.w, z, k);
        }
        __syncwarp();
    }
    float* f = &g_states[(size_t)(w * 32 + lane) * 6];
#pragma unroll
    for (int j = 0; j < 6; j++) f[j] = z[j];
}

__global__ __launch_bounds__(128) void pass_final(const float* __restrict__ x,
                                                  float* __restrict__ y,
                                                  const float* lg, const float* mg,
                                                  const float* mfc, const float* mq,
                                                  const float* hg) {
    __shared__ __align__(16) float sbuf[4][32][36];
    __shared__ __align__(16) float scoef[16];
    int wslot = threadIdx.x >> 5;
    int w = blockIdx.x * 4 + wslot;
    int lane = threadIdx.x & 31;
    float (*buf)[36] = sbuf[wslot];
    const float* xw = x + (size_t)w * (32 * CHUNK);
    float* yw = y + (size_t)w * (32 * CHUNK);

    int seg = lane >> 3;
    int off = (lane & 7) * 4;

    block_coefs(scoef, lg, mg, mfc, mq, hg);

    float z[6];
    const float* si = &g_states[(size_t)(w * 32 + lane) * 6];
#pragma unroll
    for (int j = 0; j < 6; j++) z[j] = si[j];

    float4 pre[8];
#pragma unroll
    for (int q = 0; q < 8; q++)
        pre[q] = *(const float4*)(xw + (q * 4 + seg) * CHUNK + off);
    __syncthreads();

    float k[15];
#pragma unroll
    for (int i = 0; i < 15; i++) k[i] = scoef[i];

#pragma unroll
    for (int t = 0; t < CHUNK / 32; t++) {
#pragma unroll
        for (int q = 0; q < 8; q++)
            *(float4*)&buf[q * 4 + seg][off] = pre[q];
        __syncwarp();
        if (t < CHUNK / 32 - 1) {
#pragma unroll
            for (int q = 0; q < 8; q++)
                pre[q] = *(const float4*)(xw + (q * 4 + seg) * CHUNK + (t + 1) * 32 + off);
        }
        float4* my = (float4*)buf[lane];
#pragma unroll
        for (int j = 0; j < 8; j++) {
            float4 v = my[j];
            float4 o;
            o.x = step_all(v.x, z, k);
            o.y = step_all(v.y, z, k);
            o.z = step_all(v.z, z, k);
            o.w = step_all(v.w, z, k);
            my[j] = o;
        }
        __syncwarp();
#pragma unroll
        for (int q = 0; q < 8; q++) {
            float4 v = *(const float4*)&buf[q * 4 + seg][off];
            *(float4*)(yw + (q * 4 + seg) * CHUNK + t * 32 + off) = v;
        }
        __syncwarp();
    }
}

// ------------------------------------------------------------ fused scan --

__device__ __forceinline__ void affine_step(float s[6], const float fv[6],
                                            const float T[36]) {
    float ns[6];
#pragma unroll
    for (int j = 0; j < 6; j++) {
        float acc = fv[j];
#pragma unroll
        for (int kk = 0; kk < 6; kk++) acc = fmaf(T[j * 6 + kk], s[kk], acc);
        ns[j] = acc;
    }
#pragma unroll
    for (int j = 0; j < 6; j++) s[j] = ns[j];
}

#define MATMUL(D, A_, B_)                                                     \
    do {                                                                      \
        if (tid < 36) {                                                       \
            int r_ = tid / 6, c_ = tid % 6;                                   \
            float acc_ = 0.f;                                                 \
            for (int k_ = 0; k_ < 6; k_++)                                    \
                acc_ += (A_)[r_ * 6 + k_] * (B_)[k_ * 6 + c_];                \
            (D)[tid] = acc_;                                                  \
        }                                                                     \
        __syncthreads();                                                      \
    } while (0)

// One block per row; row's 22500 floats staged in padded dynamic smem via
// float2 bulk copies (256 threads). Each block derives coefs + builds the
// T/Tg/Tsg tables in-block (~1us, amortized), then runs the 3-level scan.
__global__ __launch_bounds__(256) void scan_fused(const float* lg, const float* mg,
                                                  const float* mfc, const float* mq,
                                                  const float* hg) {
    extern __shared__ __align__(16) float sf[];   // NGROUP * GPAD floats
    __shared__ __align__(16) float scoef[16];
    __shared__ __align__(16) float sT[36], sTg[36], sTsg[36];
    __shared__ __align__(16) float M0[36], M1[36], M2[36], M3[36], M4[36];
    __shared__ __align__(16) float grp[NGROUP][6];
    __shared__ __align__(16) float sup[NSUP][6];
    int r = blockIdx.x, tid = threadIdx.x;
    float* gs = &g_states[(size_t)r * CROW * 6];

    block_coefs(scoef, lg, mg, mfc, mq, hg);

    // bulk load of row finals (all 256 threads)
    for (int i2 = tid; i2 < CROW * 6 / 2; i2 += 256) {
        int e = 2 * i2;
        int g = e / (NGSZ * 6);
        int woff = e - g * (NGSZ * 6);
        ((float2*)sf)[g * (GPAD / 2) + woff / 2] = ((const float2*)gs)[i2];
    }
    __syncthreads();

    // one-step 6x6 homogeneous matrix A: column j = step(e_j, x=0)
    if (tid < 6) {
        float zz[6] = {0, 0, 0, 0, 0, 0};
        zz[tid] = 1.0f;
        float u = 0.0f;
        float ns[6];
        for (int st = 0; st < 3; st++) {
            float b0  = scoef[st * 5 + 0], c1 = scoef[st * 5 + 1], c2 = scoef[st * 5 + 2];
            float na1 = scoef[st * 5 + 3], na2 = scoef[st * 5 + 4];
            float z1 = zz[2 * st], z2 = zz[2 * st + 1];
            float yv = b0 * u + z1;
            ns[2 * st]     = c1 * u + na1 * z1 + z2;
            ns[2 * st + 1] = c2 * u + na2 * z1;
            u = yv;
        }
        for (int i = 0; i < 6; i++) M0[i * 6 + tid] = ns[i];
    }
    __syncthreads();

    // T = A^128 (7 squarings, ends in M1)
    MATMUL(M1, M0, M0);   // A^2
    MATMUL(M0, M1, M1);   // A^4
    MATMUL(M1, M0, M0);   // A^8
    MATMUL(M0, M1, M1);   // A^16
    MATMUL(M1, M0, M0);   // A^32
    MATMUL(M0, M1, M1);   // A^64
    MATMUL(M1, M0, M0);   // A^128 = T
    if (tid < 36) { sT[tid] = M1[tid]; M0[tid] = M1[tid]; }
    __syncthreads();

    // Tg = T^30 ; Tsg = Tg^5
    MATMUL(M1, M0, M0);   // T^2
    MATMUL(M2, M1, M1);   // T^4
    MATMUL(M3, M2, M2);   // T^8
    MATMUL(M4, M3, M3);   // T^16
    MATMUL(M0, M4, M3);   // T^24
    MATMUL(M3, M0, M2);   // T^28
    MATMUL(M2, M3, M1);   // T^30 = Tg
    if (tid < 36) sTg[tid] = M2[tid];
    __syncthreads();
    MATMUL(M1, M2, M2);   // Tg^2
    MATMUL(M0, M1, M1);   // Tg^4
    MATMUL(M4, M0, M2);   // Tg^5 = Tsg
    if (tid < 36) sTsg[tid] = M4[tid];
    __syncthreads();

    // phase 1: zero-entry scan within each group -> group final
    if (tid < NGROUP) {
        float T[36];
#pragma unroll
        for (int i = 0; i < 36; i++) T[i] = sT[i];
        const float* f = &sf[tid * GPAD];
        float s[6] = {0, 0, 0, 0, 0, 0};
        for (int i = 0; i < NGSZ; i++) {
            float fv[6];
#pragma unroll
            for (int j = 0; j < 6; j++) fv[j] = f[i * 6 + j];
            affine_step(s, fv, T);
        }
#pragma unroll
        for (int j = 0; j < 6; j++) grp[tid][j] = s[j];
    }
    __syncthreads();

    // phase 2a: zero-entry scan of 5 group finals -> supergroup final
    if (tid < NSUP) {
        float T[36];
#pragma unroll
        for (int i = 0; i < 36; i++) T[i] = sTg[i];
        float s[6] = {0, 0, 0, 0, 0, 0};
        for (int i = 0; i < NSUPG; i++) affine_step(s, grp[tid * NSUPG + i], T);
#pragma unroll
        for (int j = 0; j < 6; j++) sup[tid][j] = s[j];
    }
    __syncthreads();

    // phase 2b: serial scan over supergroups; sup[] becomes entry states
    if (tid == 0) {
        float T[36];
#pragma unroll
        for (int i = 0; i < 36; i++) T[i] = sTsg[i];
        float s[6] = {0, 0, 0, 0, 0, 0};
        for (int g = 0; g < NSUP; g++) {
            float fv[6];
#pragma unroll
            for (int j = 0; j < 6; j++) { fv[j] = sup[g][j]; sup[g][j] = s[j]; }
            affine_step(s, fv, T);
        }
    }
    __syncthreads();

    // phase 2c: group entry states from supergroup entry
    if (tid < NSUP) {
        float T[36];
#pragma unroll
        for (int i = 0; i < 36; i++) T[i] = sTg[i];
        float s[6];
#pragma unroll
        for (int j = 0; j < 6; j++) s[j] = sup[tid][j];
        for (int i = 0; i < NSUPG; i++) {
            float fv[6];
            int gi = tid * NSUPG + i;
#pragma unroll
            for (int j = 0; j < 6; j++) { fv[j] = grp[gi][j]; grp[gi][j] = s[j]; }
            affine_step(s, fv, T);
        }
    }
    __syncthreads();

    // phase 3: per-chunk entry states, overwrite staged finals
    if (tid < NGROUP) {
        float T[36];
#pragma unroll
        for (int i = 0; i < 36; i++) T[i] = sT[i];
        float* f = &sf[tid * GPAD];
        float s[6];
#pragma unroll
        for (int j = 0; j < 6; j++) s[j] = grp[tid][j];
        for (int i = 0; i < NGSZ; i++) {
            float fv[6];
#pragma unroll
            for (int j = 0; j < 6; j++) { fv[j] = f[i * 6 + j]; f[i * 6 + j] = s[j]; }
            affine_step(s, fv, T);
        }
    }
    __syncthreads();

    for (int i2 = tid; i2 < CROW * 6 / 2; i2 += 256) {
        int e = 2 * i2;
        int g = e / (NGSZ * 6);
        int woff = e - g * (NGSZ * 6);
        ((float2*)gs)[i2] = ((const float2*)sf)[g * (GPAD / 2) + woff / 2];
    }
}

// ----------------------------------------------------------------- launch --

extern "C" void kernel_launch(void* const* d_in, const int* in_sizes, int n_in,
                              void* d_out, int out_size) {
    const float* x   = (const float*)d_in[0];
    const float* lg  = (const float*)d_in[1];
    const float* mg  = (const float*)d_in[2];
    const float* mfc = (const float*)d_in[3];
    const float* mq  = (const float*)d_in[4];
    const float* hg  = (const float*)d_in[5];
    float* y = (float*)d_out;

    cudaFuncSetAttribute(scan_fused, cudaFuncAttributeMaxDynamicSharedMemorySize,
                         SCAN_SMEM);

    pass_zero<<<PBLK, 128>>>(x, lg, mg, mfc, mq, hg);
    scan_fused<<<NROW, 256, SCAN_SMEM>>>(lg, mg, mfc, mq, hg);
    pass_final<<<PBLK, 128>>>(x, y, lg, mg, mfc, mq, hg);
}